// round 2
// baseline (speedup 1.0000x reference)
#include <cuda_runtime.h>
#include <math.h>

// Problem constants (fixed by the dataset)
#define E    32
#define T    2048
#define H    1024
#define II   512
#define KTOP 4
#define P    (T * KTOP)   // 8192 token-expert pairs

// GEMM tiling
#define TM 64
#define TN 64
#define TK 32

// ---- device scratch (no allocations allowed) ----
__device__ int   g_off[E + 1];      // pair offsets per expert (exclusive scan)
__device__ int   g_tok[P];          // token id per sorted pair
__device__ float g_w[P];            // routing weight per sorted pair
__device__ float g_hin[(size_t)P * II];  // 16 MB: silu(gate)*up per pair

// ---------------------------------------------------------------------------
__global__ void zero_out_kernel(float* __restrict__ out) {
    int i = blockIdx.x * blockDim.x + threadIdx.x;
    if (i < T * H) out[i] = 0.0f;
}

// Single block: counting sort of pairs by expert.
__global__ void build_lists(const int* __restrict__ idx, const float* __restrict__ wts) {
    __shared__ int s_cnt[E];
    __shared__ int s_pos[E];
    int tid = threadIdx.x;
    if (tid < E) s_cnt[tid] = 0;
    __syncthreads();
    for (int p = tid; p < P; p += blockDim.x)
        atomicAdd(&s_cnt[idx[p]], 1);
    __syncthreads();
    if (tid == 0) {
        int acc = 0;
        for (int e = 0; e < E; e++) {
            s_pos[e] = acc;
            g_off[e] = acc;
            acc += s_cnt[e];
        }
        g_off[E] = acc;
    }
    __syncthreads();
    for (int p = tid; p < P; p += blockDim.x) {
        int e   = idx[p];
        int pos = atomicAdd(&s_pos[e], 1);
        g_tok[pos] = p / KTOP;   // token index
        g_w[pos]   = wts[p];
    }
}

// ---------------------------------------------------------------------------
// Kernel B: per-expert GEMM  gu = hidden[tok,:] @ gate_up[e].T  then silu*up.
// grid = (E, II/TN). Each block loops over this expert's token tiles.
__global__ __launch_bounds__(256, 2)
void gateup_silu(const float* __restrict__ hidden, const float* __restrict__ gup) {
    int e     = blockIdx.x;
    int nBase = blockIdx.y * TN;
    int start = g_off[e], end = g_off[e + 1];
    if (start >= end) return;

    __shared__ float sA[TK][TM];
    __shared__ float sG[TK][TN];
    __shared__ float sU[TK][TN];
    __shared__ int   sTok[TM];

    int tid = threadIdx.x;
    int tx  = tid & 15;   // n
    int ty  = tid >> 4;   // m

    const float* gbase = gup + (size_t)e * (2 * II) * H;

    for (int t0 = start; t0 < end; t0 += TM) {
        int rem = end - t0; if (rem > TM) rem = TM;
        if (tid < TM) {
            int mm = tid < rem ? tid : rem - 1;
            sTok[tid] = g_tok[t0 + mm];
        }
        __syncthreads();

        float accG[4][4] = {};
        float accU[4][4] = {};

        for (int k0 = 0; k0 < H; k0 += TK) {
            // A tile: 64 tokens x 32 h  (coalesced along c)
            #pragma unroll
            for (int i = tid; i < TM * TK; i += 256) {
                int m = i >> 5, c = i & 31;
                sA[c][m] = hidden[(size_t)sTok[m] * H + k0 + c];
            }
            // W tiles: gate rows [nBase..), up rows [nBase+II..)
            #pragma unroll
            for (int i = tid; i < TN * TK; i += 256) {
                int n = i >> 5, c = i & 31;
                sG[c][n] = gbase[(size_t)(nBase + n) * H + k0 + c];
                sU[c][n] = gbase[(size_t)(nBase + n + II) * H + k0 + c];
            }
            __syncthreads();

            #pragma unroll
            for (int kk = 0; kk < TK; kk++) {
                float a[4], g[4], u[4];
                #pragma unroll
                for (int i = 0; i < 4; i++) a[i] = sA[kk][ty * 4 + i];
                #pragma unroll
                for (int j = 0; j < 4; j++) {
                    g[j] = sG[kk][tx * 4 + j];
                    u[j] = sU[kk][tx * 4 + j];
                }
                #pragma unroll
                for (int i = 0; i < 4; i++)
                    #pragma unroll
                    for (int j = 0; j < 4; j++) {
                        accG[i][j] += a[i] * g[j];
                        accU[i][j] += a[i] * u[j];
                    }
            }
            __syncthreads();
        }

        // silu(gate) * up -> scratch, indexed by sorted pair id (contiguous rows)
        #pragma unroll
        for (int i = 0; i < 4; i++) {
            int m = ty * 4 + i;
            if (m < rem) {
                size_t row = (size_t)(t0 + m) * II + nBase;
                #pragma unroll
                for (int j = 0; j < 4; j++) {
                    float gate = accG[i][j];
                    float s    = gate / (1.0f + __expf(-gate));
                    g_hin[row + tx * 4 + j] = s * accU[i][j];
                }
            }
        }
        __syncthreads();
    }
}

// ---------------------------------------------------------------------------
// Kernel C: per-expert GEMM  out[tok,:] += w * (hin @ down[e].T)
// grid = (E, H/TN). Atomic accumulate into out (tokens span multiple experts).
__global__ __launch_bounds__(256, 2)
void down_acc(const float* __restrict__ down, float* __restrict__ out) {
    int e     = blockIdx.x;
    int hBase = blockIdx.y * TN;
    int start = g_off[e], end = g_off[e + 1];
    if (start >= end) return;

    __shared__ float sA[TK][TM];
    __shared__ float sW[TK][TN];
    __shared__ int   sTok[TM];
    __shared__ float sWt[TM];

    int tid = threadIdx.x;
    int tx  = tid & 15;
    int ty  = tid >> 4;

    const float* wbase = down + (size_t)e * H * II;

    for (int t0 = start; t0 < end; t0 += TM) {
        int rem = end - t0; if (rem > TM) rem = TM;
        if (tid < TM) {
            int mm = tid < rem ? tid : rem - 1;
            sTok[tid] = g_tok[t0 + mm];
            sWt[tid]  = g_w[t0 + mm];
        }
        __syncthreads();

        float acc[4][4] = {};

        for (int k0 = 0; k0 < II; k0 += TK) {
            #pragma unroll
            for (int i = tid; i < TM * TK; i += 256) {
                int m = i >> 5, c = i & 31;
                int mm = m < rem ? m : rem - 1;
                sA[c][m] = g_hin[(size_t)(t0 + mm) * II + k0 + c];
            }
            #pragma unroll
            for (int i = tid; i < TN * TK; i += 256) {
                int n = i >> 5, c = i & 31;
                sW[c][n] = wbase[(size_t)(hBase + n) * II + k0 + c];
            }
            __syncthreads();

            #pragma unroll
            for (int kk = 0; kk < TK; kk++) {
                float a[4], w[4];
                #pragma unroll
                for (int i = 0; i < 4; i++) a[i] = sA[kk][ty * 4 + i];
                #pragma unroll
                for (int j = 0; j < 4; j++) w[j] = sW[kk][tx * 4 + j];
                #pragma unroll
                for (int i = 0; i < 4; i++)
                    #pragma unroll
                    for (int j = 0; j < 4; j++)
                        acc[i][j] += a[i] * w[j];
            }
            __syncthreads();
        }

        #pragma unroll
        for (int i = 0; i < 4; i++) {
            int m = ty * 4 + i;
            if (m < rem) {
                float wt  = sWt[m];
                size_t ro = (size_t)sTok[m] * H + hBase;
                #pragma unroll
                for (int j = 0; j < 4; j++)
                    atomicAdd(&out[ro + tx * 4 + j], wt * acc[i][j]);
            }
        }
        __syncthreads();
    }
}

// ---------------------------------------------------------------------------
extern "C" void kernel_launch(void* const* d_in, const int* in_sizes, int n_in,
                              void* d_out, int out_size) {
    const float* hidden = (const float*)d_in[0];   // (T, H) f32
    const int*   idx    = (const int*)  d_in[1];   // (T, K) i32
    const float* wts    = (const float*)d_in[2];   // (T, K) f32
    const float* gup    = (const float*)d_in[3];   // (E, 2I, H) f32
    const float* down   = (const float*)d_in[4];   // (E, H, I) f32
    float* out = (float*)d_out;                    // (T, H) f32

    zero_out_kernel<<<(T * H + 255) / 256, 256>>>(out);
    build_lists<<<1, 256>>>(idx, wts);
    gateup_silu<<<dim3(E, II / TN), 256>>>(hidden, gup);
    down_acc<<<dim3(E, H / TN), 256>>>(down, out);
}

// round 3
// speedup vs baseline: 1.0003x; 1.0003x over previous
#include <cuda_runtime.h>
#include <math.h>

// Problem constants (fixed by the dataset)
#define E    32
#define T    2048
#define H    1024
#define II   512
#define KTOP 4
#define P    (T * KTOP)   // 8192 token-expert pairs

// GEMM tiling
#define TM 64
#define TN 64
#define TK 32

// ---- device scratch (no allocations allowed) ----
__device__ int   g_off[E + 1];      // pair offsets per expert (exclusive scan)
__device__ int   g_tok[P];          // token id per sorted pair
__device__ float g_w[P];            // routing weight per sorted pair
__device__ float g_hin[(size_t)P * II];  // 16 MB: silu(gate)*up per pair

// ---------------------------------------------------------------------------
__global__ void zero_out_kernel(float* __restrict__ out) {
    int i = blockIdx.x * blockDim.x + threadIdx.x;
    if (i < T * H) out[i] = 0.0f;
}

// Single block: counting sort of pairs by expert.
__global__ void build_lists(const int* __restrict__ idx, const float* __restrict__ wts) {
    __shared__ int s_cnt[E];
    __shared__ int s_pos[E];
    int tid = threadIdx.x;
    if (tid < E) s_cnt[tid] = 0;
    __syncthreads();
    for (int p = tid; p < P; p += blockDim.x)
        atomicAdd(&s_cnt[idx[p]], 1);
    __syncthreads();
    if (tid == 0) {
        int acc = 0;
        for (int e = 0; e < E; e++) {
            s_pos[e] = acc;
            g_off[e] = acc;
            acc += s_cnt[e];
        }
        g_off[E] = acc;
    }
    __syncthreads();
    for (int p = tid; p < P; p += blockDim.x) {
        int e   = idx[p];
        int pos = atomicAdd(&s_pos[e], 1);
        g_tok[pos] = p / KTOP;   // token index
        g_w[pos]   = wts[p];
    }
}

// ---------------------------------------------------------------------------
// Kernel B: per-expert GEMM  gu = hidden[tok,:] @ gate_up[e].T  then silu*up.
// grid = (E, II/TN). Each block loops over this expert's token tiles.
__global__ __launch_bounds__(256, 2)
void gateup_silu(const float* __restrict__ hidden, const float* __restrict__ gup) {
    int e     = blockIdx.x;
    int nBase = blockIdx.y * TN;
    int start = g_off[e], end = g_off[e + 1];
    if (start >= end) return;

    __shared__ float sA[TK][TM];
    __shared__ float sG[TK][TN];
    __shared__ float sU[TK][TN];
    __shared__ int   sTok[TM];

    int tid = threadIdx.x;
    int tx  = tid & 15;   // n
    int ty  = tid >> 4;   // m

    const float* gbase = gup + (size_t)e * (2 * II) * H;

    for (int t0 = start; t0 < end; t0 += TM) {
        int rem = end - t0; if (rem > TM) rem = TM;
        if (tid < TM) {
            int mm = tid < rem ? tid : rem - 1;
            sTok[tid] = g_tok[t0 + mm];
        }
        __syncthreads();

        float accG[4][4] = {};
        float accU[4][4] = {};

        for (int k0 = 0; k0 < H; k0 += TK) {
            // A tile: 64 tokens x 32 h  (coalesced along c)
            #pragma unroll
            for (int i = tid; i < TM * TK; i += 256) {
                int m = i >> 5, c = i & 31;
                sA[c][m] = hidden[(size_t)sTok[m] * H + k0 + c];
            }
            // W tiles: gate rows [nBase..), up rows [nBase+II..)
            #pragma unroll
            for (int i = tid; i < TN * TK; i += 256) {
                int n = i >> 5, c = i & 31;
                sG[c][n] = gbase[(size_t)(nBase + n) * H + k0 + c];
                sU[c][n] = gbase[(size_t)(nBase + n + II) * H + k0 + c];
            }
            __syncthreads();

            #pragma unroll
            for (int kk = 0; kk < TK; kk++) {
                float a[4], g[4], u[4];
                #pragma unroll
                for (int i = 0; i < 4; i++) a[i] = sA[kk][ty * 4 + i];
                #pragma unroll
                for (int j = 0; j < 4; j++) {
                    g[j] = sG[kk][tx * 4 + j];
                    u[j] = sU[kk][tx * 4 + j];
                }
                #pragma unroll
                for (int i = 0; i < 4; i++)
                    #pragma unroll
                    for (int j = 0; j < 4; j++) {
                        accG[i][j] += a[i] * g[j];
                        accU[i][j] += a[i] * u[j];
                    }
            }
            __syncthreads();
        }

        // silu(gate) * up -> scratch, indexed by sorted pair id (contiguous rows)
        #pragma unroll
        for (int i = 0; i < 4; i++) {
            int m = ty * 4 + i;
            if (m < rem) {
                size_t row = (size_t)(t0 + m) * II + nBase;
                #pragma unroll
                for (int j = 0; j < 4; j++) {
                    float gate = accG[i][j];
                    float s    = gate / (1.0f + __expf(-gate));
                    g_hin[row + tx * 4 + j] = s * accU[i][j];
                }
            }
        }
        __syncthreads();
    }
}

// ---------------------------------------------------------------------------
// Kernel C: per-expert GEMM  out[tok,:] += w * (hin @ down[e].T)
// grid = (E, H/TN). Atomic accumulate into out (tokens span multiple experts).
__global__ __launch_bounds__(256, 2)
void down_acc(const float* __restrict__ down, float* __restrict__ out) {
    int e     = blockIdx.x;
    int hBase = blockIdx.y * TN;
    int start = g_off[e], end = g_off[e + 1];
    if (start >= end) return;

    __shared__ float sA[TK][TM];
    __shared__ float sW[TK][TN];
    __shared__ int   sTok[TM];
    __shared__ float sWt[TM];

    int tid = threadIdx.x;
    int tx  = tid & 15;
    int ty  = tid >> 4;

    const float* wbase = down + (size_t)e * H * II;

    for (int t0 = start; t0 < end; t0 += TM) {
        int rem = end - t0; if (rem > TM) rem = TM;
        if (tid < TM) {
            int mm = tid < rem ? tid : rem - 1;
            sTok[tid] = g_tok[t0 + mm];
            sWt[tid]  = g_w[t0 + mm];
        }
        __syncthreads();

        float acc[4][4] = {};

        for (int k0 = 0; k0 < II; k0 += TK) {
            #pragma unroll
            for (int i = tid; i < TM * TK; i += 256) {
                int m = i >> 5, c = i & 31;
                int mm = m < rem ? m : rem - 1;
                sA[c][m] = g_hin[(size_t)(t0 + mm) * II + k0 + c];
            }
            #pragma unroll
            for (int i = tid; i < TN * TK; i += 256) {
                int n = i >> 5, c = i & 31;
                sW[c][n] = wbase[(size_t)(hBase + n) * II + k0 + c];
            }
            __syncthreads();

            #pragma unroll
            for (int kk = 0; kk < TK; kk++) {
                float a[4], w[4];
                #pragma unroll
                for (int i = 0; i < 4; i++) a[i] = sA[kk][ty * 4 + i];
                #pragma unroll
                for (int j = 0; j < 4; j++) w[j] = sW[kk][tx * 4 + j];
                #pragma unroll
                for (int i = 0; i < 4; i++)
                    #pragma unroll
                    for (int j = 0; j < 4; j++)
                        acc[i][j] += a[i] * w[j];
            }
            __syncthreads();
        }

        #pragma unroll
        for (int i = 0; i < 4; i++) {
            int m = ty * 4 + i;
            if (m < rem) {
                float wt  = sWt[m];
                size_t ro = (size_t)sTok[m] * H + hBase;
                #pragma unroll
                for (int j = 0; j < 4; j++)
                    atomicAdd(&out[ro + tx * 4 + j], wt * acc[i][j]);
            }
        }
        __syncthreads();
    }
}

// ---------------------------------------------------------------------------
extern "C" void kernel_launch(void* const* d_in, const int* in_sizes, int n_in,
                              void* d_out, int out_size) {
    const float* hidden = (const float*)d_in[0];   // (T, H) f32
    const int*   idx    = (const int*)  d_in[1];   // (T, K) i32
    const float* wts    = (const float*)d_in[2];   // (T, K) f32
    const float* gup    = (const float*)d_in[3];   // (E, 2I, H) f32
    const float* down   = (const float*)d_in[4];   // (E, H, I) f32
    float* out = (float*)d_out;                    // (T, H) f32

    zero_out_kernel<<<(T * H + 255) / 256, 256>>>(out);
    build_lists<<<1, 256>>>(idx, wts);
    gateup_silu<<<dim3(E, II / TN), 256>>>(hidden, gup);
    down_acc<<<dim3(E, H / TN), 256>>>(down, out);
}